// round 16
// baseline (speedup 1.0000x reference)
#include <cuda_runtime.h>
#include <cuda_bf16.h>
#include <cstdint>

#define BATCH 8
#define DIM   256
#define HEADS 8
#define CH    32
#define HW    16384
#define QKV_C 768
#define KS    512          // stored K per side (hi|lo)
#define TM    128
#define TN    256
#define BKK   64
#define NITER 8            // 4 dual (Bh: Ah+Al) + 4 single (Bl: Ah)
#define NSTAGE 3

// ---------------- device scratch ----------------
__device__ float g_qkv [BATCH * QKV_C * HW];
__device__ float g_qkvd[BATCH * QKV_C * HW];
__device__ __nv_bfloat16 g_xT  [(long long)BATCH * HW * KS];
__device__ __nv_bfloat16 g_vT  [(long long)BATCH * HW * KS];
__device__ __nv_bfloat16 g_wext[QKV_C * KS];
__device__ __nv_bfloat16 g_mext[BATCH * DIM * KS];
#define GRAM_CHUNKS 16
__device__ float g_gramp[GRAM_CHUNKS * BATCH * HEADS * CH * CH];
__device__ float g_nqp  [GRAM_CHUNKS * BATCH * HEADS * CH];
__device__ float g_nkp  [GRAM_CHUNKS * BATCH * HEADS * CH];
__device__ float g_attn [BATCH * HEADS * CH * CH];
__device__ float g_M    [BATCH * DIM * DIM];

// ---------------- lazy streams/events ----------------
static cudaStream_t g_s1 = nullptr;
static cudaEvent_t g_ef = nullptr, g_ew = nullptr, g_e1 = nullptr,
                   g_e2 = nullptr, g_evA = nullptr, g_ec0 = nullptr;
static bool g_init_done = false;

// ---------------- helpers ----------------
__device__ __forceinline__ uint32_t smem_u32(const void* p) {
    uint32_t a;
    asm("{ .reg .u64 t; cvta.to.shared.u64 t, %1; cvt.u32.u64 %0, t; }" : "=r"(a) : "l"(p));
    return a;
}
#define SWZ(off) ((off) ^ (((off) >> 3) & 0x70))

#define CP_ASYNC16(smaddr, gptr) \
    asm volatile("cp.async.cg.shared.global [%0], [%1], 16;" :: "r"(smaddr), "l"(gptr) : "memory")
#define CP_COMMIT() asm volatile("cp.async.commit_group;" ::: "memory")
#define CP_WAIT0()  asm volatile("cp.async.wait_group 0;" ::: "memory")
#define CP_WAIT1()  asm volatile("cp.async.wait_group 1;" ::: "memory")

#define LDSM_X4(r0, r1, r2, r3, a) \
    asm volatile("ldmatrix.sync.aligned.m8n8.x4.shared.b16 {%0,%1,%2,%3}, [%4];" \
        : "=r"(r0), "=r"(r1), "=r"(r2), "=r"(r3) : "r"(a))
#define LDSM_X2(r0, r1, a) \
    asm volatile("ldmatrix.sync.aligned.m8n8.x2.shared.b16 {%0,%1}, [%2];" \
        : "=r"(r0), "=r"(r1) : "r"(a))

#define MMA_BF16(c, a, b) \
    asm volatile("mma.sync.aligned.m16n8k16.row.col.f32.bf16.bf16.f32 " \
        "{%0,%1,%2,%3}, {%4,%5,%6,%7}, {%8,%9}, {%0,%1,%2,%3};" \
        : "+f"((c)[0]), "+f"((c)[1]), "+f"((c)[2]), "+f"((c)[3]) \
        : "r"((a)[0]), "r"((a)[1]), "r"((a)[2]), "r"((a)[3]), "r"((b)[0]), "r"((b)[1]))

#define STG_A(st) ((st) * 65536)
#define STG_B(st) ((st) * 65536 + 32768)
#define SMEM_BYTES (NSTAGE * 65536)

// ---------------------------------------------------------------------------
// bf16x3 GEMM (proven config)
// ---------------------------------------------------------------------------
__global__ void __launch_bounds__(256, 1)
gemm_bf16x3(const __nv_bfloat16* __restrict__ A, long long asb,
            const __nv_bfloat16* __restrict__ B, long long bsb,
            float* __restrict__ C, long long csb, int N, int m_base)
{
    extern __shared__ char smem[];
    const uint32_t sb = smem_u32(smem);
    const int tid = threadIdx.x;
    const int wid = tid >> 5, lane = tid & 31;
    const int m0 = m_base + blockIdx.x * TM;
    const int n0 = blockIdx.y * TN;
    A += (long long)blockIdx.z * asb + (long long)m0 * KS;
    B += (long long)blockIdx.z * bsb + (long long)n0 * KS;
    C += (long long)blockIdx.z * csb;

    const int wm = (wid >> 2) * 64;
    const int wn = (wid & 3) * 64;

    float acc[4][8][4];
#pragma unroll
    for (int i = 0; i < 4; i++)
#pragma unroll
        for (int j = 0; j < 8; j++)
#pragma unroll
            for (int e = 0; e < 4; e++) acc[i][j][e] = 0.f;

    auto load_stage = [&](int it, int st) {
        const bool dual = (it < 4);
        const int kA0 = dual ? it : (it - 4);
        const uint32_t sa = sb + STG_A(st);
        const uint32_t sB = sb + STG_B(st);
#pragma unroll
        for (int i = 0; i < 4; i++) {
            int idx = tid + i * 256;
            int r = idx >> 3, ch = (idx & 7) * 16;
            CP_ASYNC16(sa + SWZ(r * 128 + ch), A + (long long)r * KS + kA0 * BKK + (ch >> 1));
        }
        if (dual) {
            const int kA1 = it + 4;
#pragma unroll
            for (int i = 0; i < 4; i++) {
                int idx = tid + i * 256;
                int r = idx >> 3, ch = (idx & 7) * 16;
                CP_ASYNC16(sa + 16384 + SWZ(r * 128 + ch), A + (long long)r * KS + kA1 * BKK + (ch >> 1));
            }
        }
#pragma unroll
        for (int i = 0; i < 8; i++) {
            int idx = tid + i * 256;
            int r = idx >> 3, ch = (idx & 7) * 16;
            CP_ASYNC16(sB + SWZ(r * 128 + ch), B + (long long)r * KS + it * BKK + (ch >> 1));
        }
        CP_COMMIT();
    };

    load_stage(0, 0);
    load_stage(1, 1);

    const int a_row_in16 = lane & 15;
    const int a_kbyte    = (lane & 16) ? 16 : 0;
    const int b_row_in8  = lane & 7;
    const int b_kbyte    = (lane & 8) ? 16 : 0;

    for (int it = 0; it < NITER; it++) {
        const int st = it % NSTAGE;
        if (it + 1 < NITER) CP_WAIT1(); else CP_WAIT0();
        __syncthreads();
        if (it + 2 < NITER) load_stage(it + 2, (it + 2) % NSTAGE);

        const uint32_t sa0 = sb + STG_A(st);
        const uint32_t sa1 = sa0 + 16384;
        const uint32_t sB  = sb + STG_B(st);
        const bool dual = (it < 4);

#pragma unroll
        for (int ks = 0; ks < 4; ks++) {
            uint32_t bfr[8][2];
#pragma unroll
            for (int nj = 0; nj < 8; nj++) {
                int row = wn + nj * 8 + b_row_in8;
                LDSM_X2(bfr[nj][0], bfr[nj][1], sB + SWZ(row * 128 + ks * 32 + b_kbyte));
            }
            uint32_t afr[4][4];
#pragma unroll
            for (int mi = 0; mi < 4; mi++) {
                int row = wm + mi * 16 + a_row_in16;
                LDSM_X4(afr[mi][0], afr[mi][1], afr[mi][2], afr[mi][3],
                        sa0 + SWZ(row * 128 + ks * 32 + a_kbyte));
            }
#pragma unroll
            for (int mi = 0; mi < 4; mi++)
#pragma unroll
                for (int nj = 0; nj < 8; nj++)
                    MMA_BF16(acc[mi][nj], afr[mi], bfr[nj]);

            if (dual) {
#pragma unroll
                for (int mi = 0; mi < 4; mi++) {
                    int row = wm + mi * 16 + a_row_in16;
                    LDSM_X4(afr[mi][0], afr[mi][1], afr[mi][2], afr[mi][3],
                            sa1 + SWZ(row * 128 + ks * 32 + a_kbyte));
                }
#pragma unroll
                for (int mi = 0; mi < 4; mi++)
#pragma unroll
                    for (int nj = 0; nj < 8; nj++)
                        MMA_BF16(acc[mi][nj], afr[mi], bfr[nj]);
            }
        }
    }

    const int g = lane >> 2, q = lane & 3;
#pragma unroll
    for (int mi = 0; mi < 4; mi++) {
#pragma unroll
        for (int nj = 0; nj < 8; nj++) {
            int row = m0 + wm + mi * 16 + g;
            int col = n0 + wn + nj * 8 + q * 2;
            float* p0 = C + (long long)row * N + col;
            float* p1 = C + (long long)(row + 8) * N + col;
            *(float2*)p0 = make_float2(acc[mi][nj][0], acc[mi][nj][1]);
            *(float2*)p1 = make_float2(acc[mi][nj][2], acc[mi][nj][3]);
        }
    }
}

// ---------------------------------------------------------------------------
// transpose + bf16 hi/lo split: in [C=256, HW] fp32 -> out[b][n][KS]
// n_base: pixel offset of this launch's slice.
// ---------------------------------------------------------------------------
__global__ void convT_kernel(const float* __restrict__ in, long long bstride_in,
                             __nv_bfloat16* __restrict__ out, int n_base)
{
    const int b = blockIdx.z, c0 = blockIdx.y * 32, n0 = n_base + blockIdx.x * 64;
    __shared__ float s[32][65];
    const int t = threadIdx.x;
    {
        int c = t >> 3, nq = (t & 7) * 8;
        const float* p = in + (long long)b * bstride_in + (long long)(c0 + c) * HW + n0 + nq;
        float4 v0 = *(const float4*)p;
        float4 v1 = *(const float4*)(p + 4);
        s[c][nq + 0] = v0.x; s[c][nq + 1] = v0.y; s[c][nq + 2] = v0.z; s[c][nq + 3] = v0.w;
        s[c][nq + 4] = v1.x; s[c][nq + 5] = v1.y; s[c][nq + 6] = v1.z; s[c][nq + 7] = v1.w;
    }
    __syncthreads();
    {
        int nl = t >> 2, kq = (t & 3) * 8;
        __nv_bfloat16 hi[8], lo[8];
#pragma unroll
        for (int j = 0; j < 8; j++) {
            float v = s[kq + j][nl];
            hi[j] = __float2bfloat16(v);
            lo[j] = __float2bfloat16(v - __bfloat162float(hi[j]));
        }
        __nv_bfloat16* op = out + (long long)b * ((long long)HW * KS) + (long long)(n0 + nl) * KS + c0 + kq;
        *(uint4*)op         = *(uint4*)hi;
        *(uint4*)(op + 256) = *(uint4*)lo;
    }
}

// A-side split: in [M,256] fp32 -> out [M,KS] bf16, hi at k, lo at k+256
__global__ void convA_kernel(const float* __restrict__ in, long long bstride_in,
                             __nv_bfloat16* __restrict__ out, long long bstride_out)
{
    const int m = blockIdx.x, b = blockIdx.y, k = threadIdx.x;
    float v = in[(long long)b * bstride_in + (long long)m * 256 + k];
    __nv_bfloat16 hi = __float2bfloat16(v);
    __nv_bfloat16 lo = __float2bfloat16(v - __bfloat162float(hi));
    __nv_bfloat16* op = out + (long long)b * bstride_out + (long long)m * KS + k;
    op[0] = hi; op[256] = lo;
}

// ---------------------------------------------------------------------------
// Depthwise 3x3, SAME. Each thread: 2 output rows x 4 px.
// o_base: channel offset; y_base: image-row offset of this launch's slice.
// ---------------------------------------------------------------------------
__global__ void __launch_bounds__(256)
dwconv_kernel(const float* __restrict__ in,
              const float* __restrict__ wdw,
              float* __restrict__ out, int o_base, int y_base)
{
    const int o = o_base + blockIdx.y, b = blockIdx.z;
    const int y0 = y_base + blockIdx.x * 16 + (threadIdx.x >> 5) * 2;
    const int c = (threadIdx.x & 31) * 4;

    __shared__ float w[9];
    if (threadIdx.x < 9) w[threadIdx.x] = wdw[o * 27 + 9 + threadIdx.x];
    __syncthreads();

    const float* ip = in + (long long)(b * QKV_C + o) * HW;

    float row[4][6];
#pragma unroll
    for (int r = 0; r < 4; r++) {
        int yy = y0 + r - 1;
        if (yy < 0 || yy > 127) {
#pragma unroll
            for (int j = 0; j < 6; j++) row[r][j] = 0.f;
        } else {
            const float* rp = ip + yy * 128;
            float4 m = *(const float4*)(rp + c);
            row[r][0] = (c > 0)   ? __ldg(rp + c - 1) : 0.f;
            row[r][1] = m.x; row[r][2] = m.y; row[r][3] = m.z; row[r][4] = m.w;
            row[r][5] = (c < 124) ? __ldg(rp + c + 4) : 0.f;
        }
    }

    float* op = out + (long long)(b * QKV_C + o) * HW + y0 * 128 + c;
#pragma unroll
    for (int oy = 0; oy < 2; oy++) {
        float4 res;
        float* rf = (float*)&res;
#pragma unroll
        for (int x = 0; x < 4; x++) {
            rf[x] = w[0] * row[oy][x]     + w[1] * row[oy][x + 1]     + w[2] * row[oy][x + 2]
                  + w[3] * row[oy + 1][x] + w[4] * row[oy + 1][x + 1] + w[5] * row[oy + 1][x + 2]
                  + w[6] * row[oy + 2][x] + w[7] * row[oy + 2][x + 1] + w[8] * row[oy + 2][x + 2];
        }
        *(float4*)(op + oy * 128) = res;
    }
}

// ---------------------------------------------------------------------------
__global__ void gram_kernel(const float* __restrict__ qkvd,
                            float* __restrict__ Gp,
                            float* __restrict__ NQp,
                            float* __restrict__ NKp)
{
    const int chunk = blockIdx.x;
    const int h = blockIdx.y;
    const int b = blockIdx.z;
    const int CHN = HW / GRAM_CHUNKS;
    const int n0 = chunk * CHN;

    const float* qbase = qkvd + (long long)(b * QKV_C + h * CH) * HW;
    const float* kbase = qkvd + (long long)(b * QKV_C + DIM + h * CH) * HW;

    __shared__ float qs[32][65];
    __shared__ float ks[32][65];

    const int tid = threadIdx.x;
    const int cc = tid >> 3;
    const int d0 = (tid & 7) * 4;
    const int nr = tid >> 2;
    const int nt0 = (tid & 3) * 16;

    float acc0 = 0.f, acc1 = 0.f, acc2 = 0.f, acc3 = 0.f;
    float nacc = 0.f;

    for (int t0 = 0; t0 < CHN; t0 += 64) {
#pragma unroll
        for (int i = 0; i < 8; i++) {
            int lin = tid + i * 256;
            int c = lin >> 6, t = lin & 63;
            qs[c][t] = qbase[(long long)c * HW + n0 + t0 + t];
            ks[c][t] = kbase[(long long)c * HW + n0 + t0 + t];
        }
        __syncthreads();

#pragma unroll 8
        for (int t = 0; t < 64; t++) {
            float qv = qs[cc][t];
            acc0 += qv * ks[d0 + 0][t];
            acc1 += qv * ks[d0 + 1][t];
            acc2 += qv * ks[d0 + 2][t];
            acc3 += qv * ks[d0 + 3][t];
        }
        {
            const float* srow = (nr < 32) ? qs[nr] : ks[nr - 32];
#pragma unroll
            for (int t = 0; t < 16; t++) { float v = srow[nt0 + t]; nacc += v * v; }
        }
        __syncthreads();
    }

    const int bh = b * HEADS + h;
    float* gp = Gp + (((long long)chunk * 64 + bh) * CH + cc) * CH + d0;
    gp[0] = acc0; gp[1] = acc1; gp[2] = acc2; gp[3] = acc3;

    nacc += __shfl_down_sync(0xffffffff, nacc, 1);
    nacc += __shfl_down_sync(0xffffffff, nacc, 2);
    if ((tid & 3) == 0) {
        if (nr < 32) NQp[((long long)chunk * 64 + bh) * CH + nr]        = nacc;
        else         NKp[((long long)chunk * 64 + bh) * CH + (nr - 32)] = nacc;
    }
}

// ---------------------------------------------------------------------------
__global__ void attn_kernel(const float* __restrict__ Gp,
                            const float* __restrict__ NQp,
                            const float* __restrict__ NKp,
                            const float* __restrict__ temp,
                            float* __restrict__ A)
{
    const int bh = blockIdx.x;
    const int c = threadIdx.x;
    const int h = bh & 7;

    __shared__ float invk_s[32];

    float nq = 0.f, nk = 0.f;
    for (int ch = 0; ch < GRAM_CHUNKS; ch++) {
        nq += NQp[((long long)ch * 64 + bh) * CH + c];
        nk += NKp[((long long)ch * 64 + bh) * CH + c];
    }
    float invq = 1.f / fmaxf(sqrtf(nq), 1e-12f);
    invk_s[c]  = 1.f / fmaxf(sqrtf(nk), 1e-12f);
    __syncwarp();

    const float t = temp[h];
    float vals[32];
    float mx = -1e30f;
#pragma unroll
    for (int d = 0; d < 32; d++) {
        float g = 0.f;
        for (int ch = 0; ch < GRAM_CHUNKS; ch++)
            g += Gp[(((long long)ch * 64 + bh) * CH + c) * CH + d];
        float v = g * invq * invk_s[d] * t;
        vals[d] = v;
        mx = fmaxf(mx, v);
    }
    float s = 0.f;
#pragma unroll
    for (int d = 0; d < 32; d++) { vals[d] = expf(vals[d] - mx); s += vals[d]; }
    float inv = 1.f / s;
    float* ap = A + (long long)bh * CH * CH + c * CH;
#pragma unroll
    for (int d = 0; d < 32; d++) ap[d] = vals[d] * inv;
}

// ---------------------------------------------------------------------------
__global__ void fold_kernel(const float* __restrict__ attn,
                            const float* __restrict__ wproj,
                            float* __restrict__ Mbuf)
{
    const int h = blockIdx.x;
    const int b = blockIdx.y;
    const int o = threadIdx.x;

    __shared__ float as[32][33];
    for (int i = threadIdx.x; i < 1024; i += 256)
        as[i >> 5][i & 31] = attn[((long long)(b * HEADS + h)) * 1024 + i];
    __syncthreads();

    float wrow[32];
#pragma unroll
    for (int c = 0; c < 32; c++) wrow[c] = wproj[o * DIM + h * CH + c];

#pragma unroll 4
    for (int d = 0; d < 32; d++) {
        float acc = 0.f;
#pragma unroll
        for (int c = 0; c < 32; c++) acc += wrow[c] * as[c][d];
        Mbuf[((long long)(b * DIM + o)) * DIM + h * CH + d] = acc;
    }
}

// ---------------------------------------------------------------------------
extern "C" void kernel_launch(void* const* d_in, const int* in_sizes, int n_in,
                              void* d_out, int out_size)
{
    const float* x      = (const float*)d_in[0];
    const float* w_qkv  = (const float*)d_in[1];
    const float* w_dw   = (const float*)d_in[2];
    const float* w_proj = (const float*)d_in[3];
    const float* temp   = (const float*)d_in[4];
    float* out = (float*)d_out;

    if (!g_init_done) {
        cudaStreamCreateWithFlags(&g_s1, cudaStreamNonBlocking);
        cudaEventCreateWithFlags(&g_ef,  cudaEventDisableTiming);
        cudaEventCreateWithFlags(&g_ew,  cudaEventDisableTiming);
        cudaEventCreateWithFlags(&g_e1,  cudaEventDisableTiming);
        cudaEventCreateWithFlags(&g_e2,  cudaEventDisableTiming);
        cudaEventCreateWithFlags(&g_evA, cudaEventDisableTiming);
        cudaEventCreateWithFlags(&g_ec0, cudaEventDisableTiming);
        g_init_done = true;
    }

    float *qkv, *qkvd, *Gp, *NQp, *NKp, *ATT, *Mb;
    __nv_bfloat16 *xT, *vT, *wext, *mext;
    cudaGetSymbolAddress((void**)&qkv,  g_qkv);
    cudaGetSymbolAddress((void**)&qkvd, g_qkvd);
    cudaGetSymbolAddress((void**)&Gp,   g_gramp);
    cudaGetSymbolAddress((void**)&NQp,  g_nqp);
    cudaGetSymbolAddress((void**)&NKp,  g_nkp);
    cudaGetSymbolAddress((void**)&ATT,  g_attn);
    cudaGetSymbolAddress((void**)&Mb,   g_M);
    cudaGetSymbolAddress((void**)&xT,   g_xT);
    cudaGetSymbolAddress((void**)&vT,   g_vT);
    cudaGetSymbolAddress((void**)&wext, g_wext);
    cudaGetSymbolAddress((void**)&mext, g_mext);

    cudaFuncSetAttribute(gemm_bf16x3, cudaFuncAttributeMaxDynamicSharedMemorySize, SMEM_BYTES);

    cudaStream_t s0 = 0, s1 = g_s1;

    // legal capture fork
    cudaEventRecord(g_ef, s0);
    cudaStreamWaitEvent(s1, g_ef, 0);

    // s1: weight split (parallel with convT_x on s0)
    convA_kernel<<<dim3(QKV_C, 1), 256, 0, s1>>>(w_qkv, 0LL, wext, 0LL);
    cudaEventRecord(g_ew, s1);

    // s0: x transpose+split (whole)
    convT_kernel<<<dim3(HW / 64, DIM / 32, BATCH), 256, 0, s0>>>(x, (long long)DIM * HW, xT, 0);
    cudaStreamWaitEvent(s0, g_ew, 0);

    // s0: GEMM1 qk slice (rows 0..512), single launch
    gemm_bf16x3<<<dim3(4, HW / TN, BATCH), 256, SMEM_BYTES, s0>>>(
        wext, 0LL, xT, (long long)HW * KS, qkv, (long long)QKV_C * HW, HW, 0);
    cudaEventRecord(g_e1, s0);

    // s1: qk chain, overlaps s0 v-work
    cudaStreamWaitEvent(s1, g_e1, 0);
    dwconv_kernel<<<dim3(8, 512, BATCH), 256, 0, s1>>>(qkv, w_dw, qkvd, 0, 0);
    gram_kernel<<<dim3(GRAM_CHUNKS, HEADS, BATCH), 256, 0, s1>>>(qkvd, Gp, NQp, NKp);
    attn_kernel<<<BATCH * HEADS, 32, 0, s1>>>(Gp, NQp, NKp, temp, ATT);
    fold_kernel<<<dim3(HEADS, BATCH), 256, 0, s1>>>(ATT, w_proj, Mb);
    convA_kernel<<<dim3(DIM, BATCH), 256, 0, s1>>>(Mb, (long long)DIM * DIM, mext, (long long)DIM * KS);
    cudaEventRecord(g_e2, s1);

    // s0: GEMM1 v slice (rows 512..768)
    gemm_bf16x3<<<dim3(2, HW / TN, BATCH), 256, SMEM_BYTES, s0>>>(
        wext, 0LL, xT, (long long)HW * KS, qkv, (long long)QKV_C * HW, HW, 512);

    // v-tail ping-pong:
    // s0: dwconv_v rows 0..63 -> evA ; dwconv_v rows 64..127 ; convT_v half1
    // s1: (after qk chain) wait evA -> convT_v half0 -> ec0
    dwconv_kernel<<<dim3(4, 256, BATCH), 256, 0, s0>>>(qkv, w_dw, qkvd, 512, 0);
    cudaEventRecord(g_evA, s0);
    cudaStreamWaitEvent(s1, g_evA, 0);
    convT_kernel<<<dim3(128, DIM / 32, BATCH), 256, 0, s1>>>(
        qkvd + (long long)2 * DIM * HW, (long long)QKV_C * HW, vT, 0);
    cudaEventRecord(g_ec0, s1);

    dwconv_kernel<<<dim3(4, 256, BATCH), 256, 0, s0>>>(qkv, w_dw, qkvd, 512, 64);
    convT_kernel<<<dim3(128, DIM / 32, BATCH), 256, 0, s0>>>(
        qkvd + (long long)2 * DIM * HW, (long long)QKV_C * HW, vT, 8192);

    // join: GEMM2 needs vT halves (s0 order + ec0) and mext (e2)
    cudaStreamWaitEvent(s0, g_ec0, 0);
    cudaStreamWaitEvent(s0, g_e2, 0);
    gemm_bf16x3<<<dim3(DIM / TM, HW / TN, BATCH), 256, SMEM_BYTES, s0>>>(
        mext, (long long)DIM * KS, vT, (long long)HW * KS, out, (long long)DIM * HW, HW, 0);
}

// round 17
// speedup vs baseline: 1.0498x; 1.0498x over previous
#include <cuda_runtime.h>
#include <cuda_bf16.h>
#include <cuda_fp16.h>
#include <cstdint>

#define BATCH 8
#define DIM   256
#define HEADS 8
#define CH    32
#define HW    16384
#define QKV_C 768
#define KS    512          // bf16 stored K per side (hi|lo) for GEMM1
#define KB2   512          // fp16 B K for GEMM2 (Vh|Vl)
#define KA2   256          // fp16 A K for GEMM2 (Mh only)
#define TM    128
#define TN    256
#define BKK   64
#define NITER 8            // GEMM1: 4 dual + 4 single
#define NIT2  8            // GEMM2: 8 single chunks
#define NSTAGE 3

// ---------------- device scratch ----------------
__device__ float g_qkv [BATCH * QKV_C * HW];
__device__ float g_qkvd[BATCH * QKV_C * HW];
__device__ __nv_bfloat16 g_xT  [(long long)BATCH * HW * KS];
__device__ __half        g_vT  [(long long)BATCH * HW * KB2];
__device__ __nv_bfloat16 g_wext[QKV_C * KS];
__device__ __half        g_mh  [BATCH * DIM * KA2];
#define GRAM_CHUNKS 16
__device__ float g_gramp[GRAM_CHUNKS * BATCH * HEADS * CH * CH];
__device__ float g_nqp  [GRAM_CHUNKS * BATCH * HEADS * CH];
__device__ float g_nkp  [GRAM_CHUNKS * BATCH * HEADS * CH];
__device__ float g_attn [BATCH * HEADS * CH * CH];
__device__ float g_M    [BATCH * DIM * DIM];

// ---------------- lazy streams/events ----------------
static cudaStream_t g_s1 = nullptr;
static cudaEvent_t g_e1 = nullptr, g_e2 = nullptr;
static bool g_init_done = false;

// ---------------- helpers ----------------
__device__ __forceinline__ uint32_t smem_u32(const void* p) {
    uint32_t a;
    asm("{ .reg .u64 t; cvta.to.shared.u64 t, %1; cvt.u32.u64 %0, t; }" : "=r"(a) : "l"(p));
    return a;
}
#define SWZ(off) ((off) ^ (((off) >> 3) & 0x70))

#define CP_ASYNC16(smaddr, gptr) \
    asm volatile("cp.async.cg.shared.global [%0], [%1], 16;" :: "r"(smaddr), "l"(gptr) : "memory")
#define CP_COMMIT() asm volatile("cp.async.commit_group;" ::: "memory")
#define CP_WAIT0()  asm volatile("cp.async.wait_group 0;" ::: "memory")
#define CP_WAIT1()  asm volatile("cp.async.wait_group 1;" ::: "memory")

#define LDSM_X4(r0, r1, r2, r3, a) \
    asm volatile("ldmatrix.sync.aligned.m8n8.x4.shared.b16 {%0,%1,%2,%3}, [%4];" \
        : "=r"(r0), "=r"(r1), "=r"(r2), "=r"(r3) : "r"(a))
#define LDSM_X2(r0, r1, a) \
    asm volatile("ldmatrix.sync.aligned.m8n8.x2.shared.b16 {%0,%1}, [%2];" \
        : "=r"(r0), "=r"(r1) : "r"(a))

#define MMA_BF16(c, a, b) \
    asm volatile("mma.sync.aligned.m16n8k16.row.col.f32.bf16.bf16.f32 " \
        "{%0,%1,%2,%3}, {%4,%5,%6,%7}, {%8,%9}, {%0,%1,%2,%3};" \
        : "+f"((c)[0]), "+f"((c)[1]), "+f"((c)[2]), "+f"((c)[3]) \
        : "r"((a)[0]), "r"((a)[1]), "r"((a)[2]), "r"((a)[3]), "r"((b)[0]), "r"((b)[1]))

#define MMA_FP16(c, a, b) \
    asm volatile("mma.sync.aligned.m16n8k16.row.col.f32.f16.f16.f32 " \
        "{%0,%1,%2,%3}, {%4,%5,%6,%7}, {%8,%9}, {%0,%1,%2,%3};" \
        : "+f"((c)[0]), "+f"((c)[1]), "+f"((c)[2]), "+f"((c)[3]) \
        : "r"((a)[0]), "r"((a)[1]), "r"((a)[2]), "r"((a)[3]), "r"((b)[0]), "r"((b)[1]))

#define STG_A(st) ((st) * 65536)
#define STG_B(st) ((st) * 65536 + 32768)
#define SMEM_BYTES (NSTAGE * 65536)

// ---------------------------------------------------------------------------
// GEMM1: bf16x3 (proven config, unchanged)
// ---------------------------------------------------------------------------
__global__ void __launch_bounds__(256, 1)
gemm_bf16x3(const __nv_bfloat16* __restrict__ A, long long asb,
            const __nv_bfloat16* __restrict__ B, long long bsb,
            float* __restrict__ C, long long csb, int N, int m_base)
{
    extern __shared__ char smem[];
    const uint32_t sb = smem_u32(smem);
    const int tid = threadIdx.x;
    const int wid = tid >> 5, lane = tid & 31;
    const int m0 = m_base + blockIdx.x * TM;
    const int n0 = blockIdx.y * TN;
    A += (long long)blockIdx.z * asb + (long long)m0 * KS;
    B += (long long)blockIdx.z * bsb + (long long)n0 * KS;
    C += (long long)blockIdx.z * csb;

    const int wm = (wid >> 2) * 64;
    const int wn = (wid & 3) * 64;

    float acc[4][8][4];
#pragma unroll
    for (int i = 0; i < 4; i++)
#pragma unroll
        for (int j = 0; j < 8; j++)
#pragma unroll
            for (int e = 0; e < 4; e++) acc[i][j][e] = 0.f;

    auto load_stage = [&](int it, int st) {
        const bool dual = (it < 4);
        const int kA0 = dual ? it : (it - 4);
        const uint32_t sa = sb + STG_A(st);
        const uint32_t sB = sb + STG_B(st);
#pragma unroll
        for (int i = 0; i < 4; i++) {
            int idx = tid + i * 256;
            int r = idx >> 3, ch = (idx & 7) * 16;
            CP_ASYNC16(sa + SWZ(r * 128 + ch), A + (long long)r * KS + kA0 * BKK + (ch >> 1));
        }
        if (dual) {
            const int kA1 = it + 4;
#pragma unroll
            for (int i = 0; i < 4; i++) {
                int idx = tid + i * 256;
                int r = idx >> 3, ch = (idx & 7) * 16;
                CP_ASYNC16(sa + 16384 + SWZ(r * 128 + ch), A + (long long)r * KS + kA1 * BKK + (ch >> 1));
            }
        }
#pragma unroll
        for (int i = 0; i < 8; i++) {
            int idx = tid + i * 256;
            int r = idx >> 3, ch = (idx & 7) * 16;
            CP_ASYNC16(sB + SWZ(r * 128 + ch), B + (long long)r * KS + it * BKK + (ch >> 1));
        }
        CP_COMMIT();
    };

    load_stage(0, 0);
    load_stage(1, 1);

    const int a_row_in16 = lane & 15;
    const int a_kbyte    = (lane & 16) ? 16 : 0;
    const int b_row_in8  = lane & 7;
    const int b_kbyte    = (lane & 8) ? 16 : 0;

    for (int it = 0; it < NITER; it++) {
        const int st = it % NSTAGE;
        if (it + 1 < NITER) CP_WAIT1(); else CP_WAIT0();
        __syncthreads();
        if (it + 2 < NITER) load_stage(it + 2, (it + 2) % NSTAGE);

        const uint32_t sa0 = sb + STG_A(st);
        const uint32_t sa1 = sa0 + 16384;
        const uint32_t sB  = sb + STG_B(st);
        const bool dual = (it < 4);

#pragma unroll
        for (int ks = 0; ks < 4; ks++) {
            uint32_t bfr[8][2];
#pragma unroll
            for (int nj = 0; nj < 8; nj++) {
                int row = wn + nj * 8 + b_row_in8;
                LDSM_X2(bfr[nj][0], bfr[nj][1], sB + SWZ(row * 128 + ks * 32 + b_kbyte));
            }
            uint32_t afr[4][4];
#pragma unroll
            for (int mi = 0; mi < 4; mi++) {
                int row = wm + mi * 16 + a_row_in16;
                LDSM_X4(afr[mi][0], afr[mi][1], afr[mi][2], afr[mi][3],
                        sa0 + SWZ(row * 128 + ks * 32 + a_kbyte));
            }
#pragma unroll
            for (int mi = 0; mi < 4; mi++)
#pragma unroll
                for (int nj = 0; nj < 8; nj++)
                    MMA_BF16(acc[mi][nj], afr[mi], bfr[nj]);

            if (dual) {
#pragma unroll
                for (int mi = 0; mi < 4; mi++) {
                    int row = wm + mi * 16 + a_row_in16;
                    LDSM_X4(afr[mi][0], afr[mi][1], afr[mi][2], afr[mi][3],
                            sa1 + SWZ(row * 128 + ks * 32 + a_kbyte));
                }
#pragma unroll
                for (int mi = 0; mi < 4; mi++)
#pragma unroll
                    for (int nj = 0; nj < 8; nj++)
                        MMA_BF16(acc[mi][nj], afr[mi], bfr[nj]);
            }
        }
    }

    const int g = lane >> 2, q = lane & 3;
#pragma unroll
    for (int mi = 0; mi < 4; mi++) {
#pragma unroll
        for (int nj = 0; nj < 8; nj++) {
            int row = m0 + wm + mi * 16 + g;
            int col = n0 + wn + nj * 8 + q * 2;
            float* p0 = C + (long long)row * N + col;
            float* p1 = C + (long long)(row + 8) * N + col;
            *(float2*)p0 = make_float2(acc[mi][nj][0], acc[mi][nj][1]);
            *(float2*)p1 = make_float2(acc[mi][nj][2], acc[mi][nj][3]);
        }
    }
}

// ---------------------------------------------------------------------------
// GEMM2: fp16 2-term.  C = Mh @ [Vh|Vl]^T  (A fp16 K=256, B fp16 K=512)
// grid (DIM/TM, HW/TN, BATCH), same pipeline, 8 single chunks.
// ---------------------------------------------------------------------------
__global__ void __launch_bounds__(256, 1)
gemm2_fp16(const __half* __restrict__ A, long long asb,
           const __half* __restrict__ B, long long bsb,
           float* __restrict__ C, long long csb, int N)
{
    extern __shared__ char smem[];
    const uint32_t sb = smem_u32(smem);
    const int tid = threadIdx.x;
    const int wid = tid >> 5, lane = tid & 31;
    const int m0 = blockIdx.x * TM;
    const int n0 = blockIdx.y * TN;
    A += (long long)blockIdx.z * asb + (long long)m0 * KA2;
    B += (long long)blockIdx.z * bsb + (long long)n0 * KB2;
    C += (long long)blockIdx.z * csb;

    const int wm = (wid >> 2) * 64;
    const int wn = (wid & 3) * 64;

    float acc[4][8][4];
#pragma unroll
    for (int i = 0; i < 4; i++)
#pragma unroll
        for (int j = 0; j < 8; j++)
#pragma unroll
            for (int e = 0; e < 4; e++) acc[i][j][e] = 0.f;

    auto load_stage = [&](int it, int st) {
        const int kA = it & 3;           // Mh chunk (K=256)
        const uint32_t sa = sb + STG_A(st);
        const uint32_t sB = sb + STG_B(st);
#pragma unroll
        for (int i = 0; i < 4; i++) {
            int idx = tid + i * 256;
            int r = idx >> 3, ch = (idx & 7) * 16;
            CP_ASYNC16(sa + SWZ(r * 128 + ch), A + (long long)r * KA2 + kA * BKK + (ch >> 1));
        }
#pragma unroll
        for (int i = 0; i < 8; i++) {
            int idx = tid + i * 256;
            int r = idx >> 3, ch = (idx & 7) * 16;
            CP_ASYNC16(sB + SWZ(r * 128 + ch), B + (long long)r * KB2 + it * BKK + (ch >> 1));
        }
        CP_COMMIT();
    };

    load_stage(0, 0);
    load_stage(1, 1);

    const int a_row_in16 = lane & 15;
    const int a_kbyte    = (lane & 16) ? 16 : 0;
    const int b_row_in8  = lane & 7;
    const int b_kbyte    = (lane & 8) ? 16 : 0;

    for (int it = 0; it < NIT2; it++) {
        const int st = it % NSTAGE;
        if (it + 1 < NIT2) CP_WAIT1(); else CP_WAIT0();
        __syncthreads();
        if (it + 2 < NIT2) load_stage(it + 2, (it + 2) % NSTAGE);

        const uint32_t sa0 = sb + STG_A(st);
        const uint32_t sB  = sb + STG_B(st);

#pragma unroll
        for (int ks = 0; ks < 4; ks++) {
            uint32_t bfr[8][2];
#pragma unroll
            for (int nj = 0; nj < 8; nj++) {
                int row = wn + nj * 8 + b_row_in8;
                LDSM_X2(bfr[nj][0], bfr[nj][1], sB + SWZ(row * 128 + ks * 32 + b_kbyte));
            }
            uint32_t afr[4][4];
#pragma unroll
            for (int mi = 0; mi < 4; mi++) {
                int row = wm + mi * 16 + a_row_in16;
                LDSM_X4(afr[mi][0], afr[mi][1], afr[mi][2], afr[mi][3],
                        sa0 + SWZ(row * 128 + ks * 32 + a_kbyte));
            }
#pragma unroll
            for (int mi = 0; mi < 4; mi++)
#pragma unroll
                for (int nj = 0; nj < 8; nj++)
                    MMA_FP16(acc[mi][nj], afr[mi], bfr[nj]);
        }
    }

    const int g = lane >> 2, q = lane & 3;
#pragma unroll
    for (int mi = 0; mi < 4; mi++) {
#pragma unroll
        for (int nj = 0; nj < 8; nj++) {
            int row = m0 + wm + mi * 16 + g;
            int col = n0 + wn + nj * 8 + q * 2;
            float* p0 = C + (long long)row * N + col;
            float* p1 = C + (long long)(row + 8) * N + col;
            *(float2*)p0 = make_float2(acc[mi][nj][0], acc[mi][nj][1]);
            *(float2*)p1 = make_float2(acc[mi][nj][2], acc[mi][nj][3]);
        }
    }
}

// ---------------------------------------------------------------------------
// transpose + bf16 hi/lo split: in [C=256, HW] fp32 -> out[b][n][KS]  (x path)
// ---------------------------------------------------------------------------
__global__ void convT_kernel(const float* __restrict__ in, long long bstride_in,
                             __nv_bfloat16* __restrict__ out)
{
    const int b = blockIdx.z, c0 = blockIdx.y * 32, n0 = blockIdx.x * 64;
    __shared__ float s[32][65];
    const int t = threadIdx.x;
    {
        int c = t >> 3, nq = (t & 7) * 8;
        const float* p = in + (long long)b * bstride_in + (long long)(c0 + c) * HW + n0 + nq;
        float4 v0 = *(const float4*)p;
        float4 v1 = *(const float4*)(p + 4);
        s[c][nq + 0] = v0.x; s[c][nq + 1] = v0.y; s[c][nq + 2] = v0.z; s[c][nq + 3] = v0.w;
        s[c][nq + 4] = v1.x; s[c][nq + 5] = v1.y; s[c][nq + 6] = v1.z; s[c][nq + 7] = v1.w;
    }
    __syncthreads();
    {
        int nl = t >> 2, kq = (t & 3) * 8;
        __nv_bfloat16 hi[8], lo[8];
#pragma unroll
        for (int j = 0; j < 8; j++) {
            float v = s[kq + j][nl];
            hi[j] = __float2bfloat16(v);
            lo[j] = __float2bfloat16(v - __bfloat162float(hi[j]));
        }
        __nv_bfloat16* op = out + (long long)b * ((long long)HW * KS) + (long long)(n0 + nl) * KS + c0 + kq;
        *(uint4*)op         = *(uint4*)hi;
        *(uint4*)(op + 256) = *(uint4*)lo;
    }
}

// ---------------------------------------------------------------------------
// transpose + fp16 hi/lo split (v path): in [C=256, HW] fp32 -> out[b][n][KB2]
// ---------------------------------------------------------------------------
__global__ void convT_h_kernel(const float* __restrict__ in, long long bstride_in,
                               __half* __restrict__ out)
{
    const int b = blockIdx.z, c0 = blockIdx.y * 32, n0 = blockIdx.x * 64;
    __shared__ float s[32][65];
    const int t = threadIdx.x;
    {
        int c = t >> 3, nq = (t & 7) * 8;
        const float* p = in + (long long)b * bstride_in + (long long)(c0 + c) * HW + n0 + nq;
        float4 v0 = *(const float4*)p;
        float4 v1 = *(const float4*)(p + 4);
        s[c][nq + 0] = v0.x; s[c][nq + 1] = v0.y; s[c][nq + 2] = v0.z; s[c][nq + 3] = v0.w;
        s[c][nq + 4] = v1.x; s[c][nq + 5] = v1.y; s[c][nq + 6] = v1.z; s[c][nq + 7] = v1.w;
    }
    __syncthreads();
    {
        int nl = t >> 2, kq = (t & 3) * 8;
        __half hi[8], lo[8];
#pragma unroll
        for (int j = 0; j < 8; j++) {
            float v = s[kq + j][nl];
            hi[j] = __float2half(v);
            lo[j] = __float2half(v - __half2float(hi[j]));
        }
        __half* op = out + (long long)b * ((long long)HW * KB2) + (long long)(n0 + nl) * KB2 + c0 + kq;
        *(uint4*)op         = *(uint4*)hi;
        *(uint4*)(op + 256) = *(uint4*)lo;
    }
}

// A-side bf16 split (weights): in [M,256] fp32 -> out [M,KS] bf16
__global__ void convA_kernel(const float* __restrict__ in, long long bstride_in,
                             __nv_bfloat16* __restrict__ out, long long bstride_out)
{
    const int m = blockIdx.x, b = blockIdx.y, k = threadIdx.x;
    float v = in[(long long)b * bstride_in + (long long)m * 256 + k];
    __nv_bfloat16 hi = __float2bfloat16(v);
    __nv_bfloat16 lo = __float2bfloat16(v - __bfloat162float(hi));
    __nv_bfloat16* op = out + (long long)b * bstride_out + (long long)m * KS + k;
    op[0] = hi; op[256] = lo;
}

// M hi-only fp16: in [M,256] fp32 -> out [M,KA2] fp16
__global__ void convA_h_kernel(const float* __restrict__ in,
                               __half* __restrict__ out)
{
    const int m = blockIdx.x, b = blockIdx.y, k = threadIdx.x;
    float v = in[((long long)b * DIM + m) * 256 + k];
    out[((long long)b * DIM + m) * KA2 + k] = __float2half(v);
}

// ---------------------------------------------------------------------------
// Depthwise 3x3, SAME. Each thread: 2 output rows x 4 px.
// ---------------------------------------------------------------------------
__global__ void __launch_bounds__(256)
dwconv_kernel(const float* __restrict__ in,
              const float* __restrict__ wdw,
              float* __restrict__ out, int o_base)
{
    const int o = o_base + blockIdx.y, b = blockIdx.z;
    const int y0 = blockIdx.x * 16 + (threadIdx.x >> 5) * 2;
    const int c = (threadIdx.x & 31) * 4;

    __shared__ float w[9];
    if (threadIdx.x < 9) w[threadIdx.x] = wdw[o * 27 + 9 + threadIdx.x];
    __syncthreads();

    const float* ip = in + (long long)(b * QKV_C + o) * HW;

    float row[4][6];
#pragma unroll
    for (int r = 0; r < 4; r++) {
        int yy = y0 + r - 1;
        if (yy < 0 || yy > 127) {
#pragma unroll
            for (int j = 0; j < 6; j++) row[r][j] = 0.f;
        } else {
            const float* rp = ip + yy * 128;
            float4 m = *(const float4*)(rp + c);
            row[r][0] = (c > 0)   ? __ldg(rp + c - 1) : 0.f;
            row[r][1] = m.x; row[r][2] = m.y; row[r][3] = m.z; row[r][4] = m.w;
            row[r][5] = (c < 124) ? __ldg(rp + c + 4) : 0.f;
        }
    }

    float* op = out + (long long)(b * QKV_C + o) * HW + y0 * 128 + c;
#pragma unroll
    for (int oy = 0; oy < 2; oy++) {
        float4 res;
        float* rf = (float*)&res;
#pragma unroll
        for (int x = 0; x < 4; x++) {
            rf[x] = w[0] * row[oy][x]     + w[1] * row[oy][x + 1]     + w[2] * row[oy][x + 2]
                  + w[3] * row[oy + 1][x] + w[4] * row[oy + 1][x + 1] + w[5] * row[oy + 1][x + 2]
                  + w[6] * row[oy + 2][x] + w[7] * row[oy + 2][x + 1] + w[8] * row[oy + 2][x + 2];
        }
        *(float4*)(op + oy * 128) = res;
    }
}

// ---------------------------------------------------------------------------
__global__ void gram_kernel(const float* __restrict__ qkvd,
                            float* __restrict__ Gp,
                            float* __restrict__ NQp,
                            float* __restrict__ NKp)
{
    const int chunk = blockIdx.x;
    const int h = blockIdx.y;
    const int b = blockIdx.z;
    const int CHN = HW / GRAM_CHUNKS;
    const int n0 = chunk * CHN;

    const float* qbase = qkvd + (long long)(b * QKV_C + h * CH) * HW;
    const float* kbase = qkvd + (long long)(b * QKV_C + DIM + h * CH) * HW;

    __shared__ float qs[32][65];
    __shared__ float ks[32][65];

    const int tid = threadIdx.x;
    const int cc = tid >> 3;
    const int d0 = (tid & 7) * 4;
    const int nr = tid >> 2;
    const int nt0 = (tid & 3) * 16;

    float acc0 = 0.f, acc1 = 0.f, acc2 = 0.f, acc3 = 0.f;
    float nacc = 0.f;

    for (int t0 = 0; t0 < CHN; t0 += 64) {
#pragma unroll
        for (int i = 0; i < 8; i++) {
            int lin = tid + i * 256;
            int c = lin >> 6, t = lin & 63;
            qs[c][t] = qbase[(long long)c * HW + n0 + t0 + t];
            ks[c][t] = kbase[(long long)c * HW + n0 + t0 + t];
        }
        __syncthreads();

#pragma unroll 8
        for (int t = 0; t < 64; t++) {
            float qv = qs[cc][t];
            acc0 += qv * ks[d0 + 0][t];
            acc1 += qv * ks[d0 + 1][t];
            acc2 += qv * ks[d0 + 2][t];
            acc3 += qv * ks[d0 + 3][t];
        }
        {
            const float* srow = (nr < 32) ? qs[nr] : ks[nr - 32];
#pragma unroll
            for (int t = 0; t < 16; t++) { float v = srow[nt0 + t]; nacc += v * v; }
        }
        __syncthreads();
    }

    const int bh = b * HEADS + h;
    float* gp = Gp + (((long long)chunk * 64 + bh) * CH + cc) * CH + d0;
    gp[0] = acc0; gp[1] = acc1; gp[2] = acc2; gp[3] = acc3;

    nacc += __shfl_down_sync(0xffffffff, nacc, 1);
    nacc += __shfl_down_sync(0xffffffff, nacc, 2);
    if ((tid & 3) == 0) {
        if (nr < 32) NQp[((long long)chunk * 64 + bh) * CH + nr]        = nacc;
        else         NKp[((long long)chunk * 64 + bh) * CH + (nr - 32)] = nacc;
    }
}

// ---------------------------------------------------------------------------
__global__ void attn_kernel(const float* __restrict__ Gp,
                            const float* __restrict__ NQp,
                            const float* __restrict__ NKp,
                            const float* __restrict__ temp,
                            float* __restrict__ A)
{
    const int bh = blockIdx.x;
    const int c = threadIdx.x;
    const int h = bh & 7;

    __shared__ float invk_s[32];

    float nq = 0.f, nk = 0.f;
    for (int ch = 0; ch < GRAM_CHUNKS; ch++) {
        nq += NQp[((long long)ch * 64 + bh) * CH + c];
        nk += NKp[((long long)ch * 64 + bh) * CH + c];
    }
    float invq = 1.f / fmaxf(sqrtf(nq), 1e-12f);
    invk_s[c]  = 1.f / fmaxf(sqrtf(nk), 1e-12f);
    __syncwarp();

    const float t = temp[h];
    float vals[32];
    float mx = -1e30f;
#pragma unroll
    for (int d = 0; d < 32; d++) {
        float g = 0.f;
        for (int ch = 0; ch < GRAM_CHUNKS; ch++)
            g += Gp[(((long long)ch * 64 + bh) * CH + c) * CH + d];
        float v = g * invq * invk_s[d] * t;
        vals[d] = v;
        mx = fmaxf(mx, v);
    }
    float s = 0.f;
#pragma unroll
    for (int d = 0; d < 32; d++) { vals[d] = expf(vals[d] - mx); s += vals[d]; }
    float inv = 1.f / s;
    float* ap = A + (long long)bh * CH * CH + c * CH;
#pragma unroll
    for (int d = 0; d < 32; d++) ap[d] = vals[d] * inv;
}

// ---------------------------------------------------------------------------
__global__ void fold_kernel(const float* __restrict__ attn,
                            const float* __restrict__ wproj,
                            float* __restrict__ Mbuf)
{
    const int h = blockIdx.x;
    const int b = blockIdx.y;
    const int o = threadIdx.x;

    __shared__ float as[32][33];
    for (int i = threadIdx.x; i < 1024; i += 256)
        as[i >> 5][i & 31] = attn[((long long)(b * HEADS + h)) * 1024 + i];
    __syncthreads();

    float wrow[32];
#pragma unroll
    for (int c = 0; c < 32; c++) wrow[c] = wproj[o * DIM + h * CH + c];

#pragma unroll 4
    for (int d = 0; d < 32; d++) {
        float acc = 0.f;
#pragma unroll
        for (int c = 0; c < 32; c++) acc += wrow[c] * as[c][d];
        Mbuf[((long long)(b * DIM + o)) * DIM + h * CH + d] = acc;
    }
}

// ---------------------------------------------------------------------------
extern "C" void kernel_launch(void* const* d_in, const int* in_sizes, int n_in,
                              void* d_out, int out_size)
{
    const float* x      = (const float*)d_in[0];
    const float* w_qkv  = (const float*)d_in[1];
    const float* w_dw   = (const float*)d_in[2];
    const float* w_proj = (const float*)d_in[3];
    const float* temp   = (const float*)d_in[4];
    float* out = (float*)d_out;

    if (!g_init_done) {
        cudaStreamCreateWithFlags(&g_s1, cudaStreamNonBlocking);
        cudaEventCreateWithFlags(&g_e1, cudaEventDisableTiming);
        cudaEventCreateWithFlags(&g_e2, cudaEventDisableTiming);
        g_init_done = true;
    }

    float *qkv, *qkvd, *Gp, *NQp, *NKp, *ATT, *Mb;
    __nv_bfloat16 *xT, *wext;
    __half *vT, *mh;
    cudaGetSymbolAddress((void**)&qkv,  g_qkv);
    cudaGetSymbolAddress((void**)&qkvd, g_qkvd);
    cudaGetSymbolAddress((void**)&Gp,   g_gramp);
    cudaGetSymbolAddress((void**)&NQp,  g_nqp);
    cudaGetSymbolAddress((void**)&NKp,  g_nkp);
    cudaGetSymbolAddress((void**)&ATT,  g_attn);
    cudaGetSymbolAddress((void**)&Mb,   g_M);
    cudaGetSymbolAddress((void**)&xT,   g_xT);
    cudaGetSymbolAddress((void**)&vT,   g_vT);
    cudaGetSymbolAddress((void**)&wext, g_wext);
    cudaGetSymbolAddress((void**)&mh,   g_mh);

    cudaFuncSetAttribute(gemm_bf16x3, cudaFuncAttributeMaxDynamicSharedMemorySize, SMEM_BYTES);
    cudaFuncSetAttribute(gemm2_fp16,  cudaFuncAttributeMaxDynamicSharedMemorySize, SMEM_BYTES);

    cudaStream_t s0 = 0, s1 = g_s1;

    // s0: weight + x conversion (round-12 proven schedule)
    convA_kernel<<<dim3(QKV_C, 1), 256, 0, s0>>>(w_qkv, 0LL, wext, 0LL);
    convT_kernel<<<dim3(HW / 64, DIM / 32, BATCH), 256, 0, s0>>>(x, (long long)DIM * HW, xT);

    // s0: GEMM1 qk slice FIRST (rows 0..512)
    gemm_bf16x3<<<dim3(4, HW / TN, BATCH), 256, SMEM_BYTES, s0>>>(
        wext, 0LL, xT, (long long)HW * KS, qkv, (long long)QKV_C * HW, HW, 0);
    cudaEventRecord(g_e1, s0);

    // s1: qk chain (dwconv -> gram -> attn -> fold -> convA_h), overlaps s0 v-work
    cudaStreamWaitEvent(s1, g_e1, 0);
    dwconv_kernel<<<dim3(8, 512, BATCH), 256, 0, s1>>>(qkv, w_dw, qkvd, 0);
    gram_kernel<<<dim3(GRAM_CHUNKS, HEADS, BATCH), 256, 0, s1>>>(qkvd, Gp, NQp, NKp);
    attn_kernel<<<BATCH * HEADS, 32, 0, s1>>>(Gp, NQp, NKp, temp, ATT);
    fold_kernel<<<dim3(HEADS, BATCH), 256, 0, s1>>>(ATT, w_proj, Mb);
    convA_h_kernel<<<dim3(DIM, BATCH), 256, 0, s1>>>(Mb, mh);
    cudaEventRecord(g_e2, s1);

    // s0: GEMM1 v slice (rows 512..768) -> dwconv(v) -> convT_h(v)
    gemm_bf16x3<<<dim3(2, HW / TN, BATCH), 256, SMEM_BYTES, s0>>>(
        wext, 0LL, xT, (long long)HW * KS, qkv, (long long)QKV_C * HW, HW, 512);
    dwconv_kernel<<<dim3(8, 256, BATCH), 256, 0, s0>>>(qkv, w_dw, qkvd, 512);
    convT_h_kernel<<<dim3(HW / 64, DIM / 32, BATCH), 256, 0, s0>>>(
        qkvd + (long long)2 * DIM * HW, (long long)QKV_C * HW, vT);

    // join, then GEMM2 (fp16 2-term, single launch)
    cudaStreamWaitEvent(s0, g_e2, 0);
    gemm2_fp16<<<dim3(DIM / TM, HW / TN, BATCH), 256, SMEM_BYTES, s0>>>(
        mh, (long long)DIM * KA2, vT, (long long)HW * KB2, out, (long long)DIM * HW, HW);
}